// round 17
// baseline (speedup 1.0000x reference)
#include <cuda_runtime.h>
#include <math.h>

// SPUPointwise — R17 (resubmit of R16; round 16 died on "GB300 container
// failed twice" before compile/run — 6th occurrence of this kernel-independent
// broker flake; every prior unchanged-resubmit succeeded). Theory unchanged:
// instruction-bound (R15: issue=70.2%, ~62 slots/elem vs ~48 essential).
// Cuts (all exact or <=3e-9-abs identities):
//  * b1 == -0.5: mixed-class chord c1 passes through (0,-0.5) by construction
//    (reference's b1 = sl - l*a1 deviates only via the 1e-8 eps, delta<=3e-9;
//    decision-flip window |l+u| <~ 2e-8 is measure-zero). Kills b1 fma and
//    b1+b1 add: nl1 = fmaf(a1,u,-0.5), q1 = fmaf(a1,lpu,-1).
//  * a1 = (s1-0.5)*rcp(1e-8-l) — no dependency on the sl select.
//  * sl's (l<0) test -> !lgt0 (exact: both arms give -0.5 at l==0). -1 SETP.
// tanh.approx rejected: saturation destroys e^u-tail relative accuracy.
//
// Output layout: out[0..N) = nl, out[N..2N) = nu.

__device__ __forceinline__ float rcpa(float x) {
    float r; asm("rcp.approx.ftz.f32 %0, %1;" : "=f"(r) : "f"(x)); return r;
}
__device__ __forceinline__ float ex2a(float x) {
    float r; asm("ex2.approx.ftz.f32 %0, %1;" : "=f"(r) : "f"(x)); return r;
}

__device__ __forceinline__ void spu_bounds(float l, float u, float& nl, float& nu) {
    const float NLOG2E = -1.44269504088896340736f;

    const float lpu = l + u;
    const float mid = 0.5f * lpu;

    const bool neg  = (u < 0.0f);
    const bool lgt0 = (l > 0.0f);

    // two sigmoids, one shared rcp: s1 = sigmoid(neg ? u : l), s2 = sigmoid(mid)
    const float x1 = neg ? u : l;
    const float e1 = ex2a(NLOG2E * x1);
    const float e2 = ex2a(NLOG2E * mid);
    const float d1 = 1.0f + e1;
    const float d2 = 1.0f + e2;
    const float r  = rcpa(d1 * d2);
    const float s1 = d2 * r;   // sigmoid(x1)
    const float s2 = d1 * r;   // sigmoid(mid)

    // endpoints (suq valid wherever consumed: u>=0 there; sl dead in neg class)
    const float suq = fmaf(u, u, -0.5f);
    const float sl  = lgt0 ? fmaf(l, l, -0.5f) : -s1;

    // neg upper: tangent at mid (grad = s^2-s, spu = -s), evaluated at l
    const float a_tn = fmaf(s2, s2, -s2);
    const float b_tn = fmaf(-a_tn, mid, -s2);
    const float nu_neg = fmaf(a_tn, l, b_tn);

    // pos lower: tangent at mid (quadratic branch), evaluated at l
    const float nl_pos = fmaf(lpu, l, fmaf(-mid, mid, -0.5f));

    // mixed lower candidates; c1 chord has intercept exactly -0.5
    const float a1  = (s1 - 0.5f) * rcpa(1e-8f - l);   // <= 0 in mixed class
    const float nl1 = fmaf(a1, u, -0.5f);              // eval at u (a1<=0)
    const float q1  = fmaf(a1, lpu, -1.0f);
    const float q2p = fmaf(u, fmaf(0.5f, u, l), -1.0f);
    const float nl2 = fmaf(u, fmaf(-0.25f, u, l), -0.5f);  // u*l - u^2/4 - 0.5

    const bool tu = (suq > sl);                        // "normal"
    const bool c1 = (q1 > -1.0f);
    const bool c2 = tu && (q2p > q1) && (q2p > -1.0f); // q2 > max(q1, q0)

    const float nl_m = c2 ? nl2 : (c1 ? nl1 : -0.5f);

    // class merge (neg => l<0 => !lgt0, nesting safe)
    nl = neg ? -s1    : (lgt0 ? nl_pos : nl_m);
    nu = neg ? nu_neg : fmaxf(suq, sl);                // == tu ? su : sl
}

__global__ void __launch_bounds__(256, 8)
spu_pointwise_kernel(const float4* __restrict__ l4,
                     const float4* __restrict__ u4,
                     float4* __restrict__ nl4,
                     float4* __restrict__ nu4,
                     int n4) {
    int i = blockIdx.x * blockDim.x + threadIdx.x;
    if (i >= n4) return;

    const float4 lv = l4[i];
    const float4 uv = u4[i];
    float4 nlv, nuv;
    spu_bounds(lv.x, uv.x, nlv.x, nuv.x);
    spu_bounds(lv.y, uv.y, nlv.y, nuv.y);
    spu_bounds(lv.z, uv.z, nlv.z, nuv.z);
    spu_bounds(lv.w, uv.w, nlv.w, nuv.w);
    nl4[i] = nlv;
    nu4[i] = nuv;
}

// scalar tail (n not divisible by 4)
__global__ void __launch_bounds__(256, 8)
spu_pointwise_tail(const float* __restrict__ l,
                   const float* __restrict__ u,
                   float* __restrict__ nl,
                   float* __restrict__ nu,
                   int start, int n) {
    int i = start + blockIdx.x * blockDim.x + threadIdx.x;
    if (i >= n) return;
    spu_bounds(l[i], u[i], nl[i], nu[i]);
}

extern "C" void kernel_launch(void* const* d_in, const int* in_sizes, int n_in,
                              void* d_out, int out_size) {
    const float* l = (const float*)d_in[0];
    const float* u = (const float*)d_in[1];
    float* out = (float*)d_out;
    const int n = in_sizes[0];
    float* nl = out;
    float* nu = out + n;

    const int n4 = n >> 2;
    if (n4 > 0) {
        const int threads = 256;
        const int blocks = (n4 + threads - 1) / threads;
        spu_pointwise_kernel<<<blocks, threads>>>(
            (const float4*)l, (const float4*)u,
            (float4*)nl, (float4*)nu, n4);
    }
    const int rem_start = n4 << 2;
    if (rem_start < n) {
        const int rem = n - rem_start;
        spu_pointwise_tail<<<(rem + 255) / 256, 256>>>(l, u, nl, nu, rem_start, n);
    }
}